// round 2
// baseline (speedup 1.0000x reference)
#include <cuda_runtime.h>
#include <math.h>

// Problem constants
#define B_   64
#define C_   256
#define T_   32
#define H_   7
#define W_   7
#define HW_  49
#define N_   1568          // T*H*W
#define D_   512
#define KV_  97
#define KN_  300
#define NTOK 392
#define TAPS 9
#define KTOT (C_ * TAPS)   // 2304

// Device scratch (static allocation only — no cudaMalloc allowed)
__device__ float g_wt[KTOT * D_];      // transposed conv weights: [(c*9+tap)][d]
__device__ float g_cam[B_ * N_];       // cam_gt
__device__ float g_loss;

// ---------------------------------------------------------------------------
// zero / finalize
// ---------------------------------------------------------------------------
__global__ void zero_loss_kernel() { g_loss = 0.0f; }

__global__ void finalize_kernel(float* out) {
    out[0] = g_loss * (1.0f / (float)(B_ * T_ * HW_));
}

// ---------------------------------------------------------------------------
// weight transpose: conv_w (D, C, 1, 3, 3) -> g_wt[(c*9+tap)*512 + d]
// ---------------------------------------------------------------------------
__global__ void transpose_w_kernel(const float* __restrict__ cw) {
    int idx = blockIdx.x * 256 + threadIdx.x;
    if (idx >= KTOT * D_) return;
    int d  = idx & (D_ - 1);
    int ct = idx >> 9;               // c*9 + tap
    g_wt[ct * D_ + d] = cw[d * KTOT + ct];
}

// ---------------------------------------------------------------------------
// CAM kernel: one block per batch sample
// ---------------------------------------------------------------------------
__device__ __forceinline__ int block_argmax(const float* __restrict__ v, int K,
                                            float* rv, int* ri) {
    int tid = threadIdx.x;
    float best = -INFINITY;
    int bi = 0x7fffffff;
    for (int k = tid; k < K; k += 256) {
        float val = v[k];
        if (val > best) { best = val; bi = k; }
    }
    rv[tid] = best; ri[tid] = bi;
    __syncthreads();
    for (int s = 128; s > 0; s >>= 1) {
        if (tid < s) {
            float ov = rv[tid + s];
            int   oi = ri[tid + s];
            if (ov > rv[tid] || (ov == rv[tid] && oi < ri[tid])) {
                rv[tid] = ov; ri[tid] = oi;
            }
        }
        __syncthreads();
    }
    int r = ri[0];
    __syncthreads();
    return r;
}

// normalize row in-place (min-max) and return the 392nd-largest value (exact,
// via bitonic sort of padded 2048 buffer)
__device__ float norm_and_threshold(float* row, float* sbuf,
                                    float* rmin, float* rmax) {
    int tid = threadIdx.x;
    float mn = INFINITY, mx = -INFINITY;
    for (int n = tid; n < N_; n += 256) {
        float v = row[n];
        mn = fminf(mn, v);
        mx = fmaxf(mx, v);
    }
    rmin[tid] = mn; rmax[tid] = mx;
    __syncthreads();
    for (int s = 128; s > 0; s >>= 1) {
        if (tid < s) {
            rmin[tid] = fminf(rmin[tid], rmin[tid + s]);
            rmax[tid] = fmaxf(rmax[tid], rmax[tid + s]);
        }
        __syncthreads();
    }
    mn = rmin[0]; mx = rmax[0];
    __syncthreads();
    float inv = 1.0f / (mx - mn);
    for (int n = tid; n < N_; n += 256)
        row[n] = (row[n] - mn) * inv;
    __syncthreads();
    // fill sort buffer (values are in [0,1]; pad with -1)
    for (int i = tid; i < 2048; i += 256)
        sbuf[i] = (i < N_) ? row[i] : -1.0f;
    __syncthreads();
    // bitonic sort ascending
    for (int k = 2; k <= 2048; k <<= 1) {
        for (int j = k >> 1; j > 0; j >>= 1) {
            for (int i = tid; i < 2048; i += 256) {
                int ixj = i ^ j;
                if (ixj > i) {
                    float a = sbuf[i], c = sbuf[ixj];
                    bool up = ((i & k) == 0);
                    if ((a > c) == up) { sbuf[i] = c; sbuf[ixj] = a; }
                }
            }
            __syncthreads();
        }
    }
    float thr = sbuf[2048 - NTOK];   // 392nd largest
    __syncthreads();
    return thr;
}

__global__ void __launch_bounds__(256) cam_kernel(
    const float* __restrict__ x,
    const float* __restrict__ lv, const float* __restrict__ ln,
    const float* __restrict__ wpv, const float* __restrict__ wpn) {
    __shared__ float wsv[C_], wsn[C_];
    __shared__ float rowv[N_], rown[N_];
    __shared__ float sbuf[2048];
    __shared__ float rA[256];
    __shared__ float rB[256];
    __shared__ int   rI[256];

    int tid = threadIdx.x;
    int b = blockIdx.x;

    int topv = block_argmax(lv + b * KV_, KV_, rA, rI);
    int topn = block_argmax(ln + b * KN_, KN_, rA, rI);

    if (tid < C_) {
        wsv[tid] = wpv[topv * C_ + tid];
        wsn[tid] = wpn[topn * C_ + tid];
    }
    __syncthreads();

    const float* xb = x + (size_t)b * C_ * N_;
    for (int n = tid; n < N_; n += 256) {
        float av = 0.0f, an = 0.0f;
#pragma unroll 8
        for (int c = 0; c < C_; c++) {
            float xv = xb[(size_t)c * N_ + n];
            av = fmaf(wsv[c], xv, av);
            an = fmaf(wsn[c], xv, an);
        }
        rowv[n] = av; rown[n] = an;
    }
    __syncthreads();

    float thrv = norm_and_threshold(rowv, sbuf, rA, rB);
    float thrn = norm_and_threshold(rown, sbuf, rA, rB);

    for (int n = tid; n < N_; n += 256) {
        float cv = (rowv[n] >= thrv) ? rowv[n] : 0.0f;
        float cn = (rown[n] >= thrn) ? rown[n] : 0.0f;
        g_cam[b * N_ + n] = fmaxf(cv, cn);
    }
}

// ---------------------------------------------------------------------------
// Fused conv3x3 (pad 1) + bias + relu + score 1x1 + BCE-with-logits sum.
// One block per (b, t) plane. Each thread owns one output channel d per pass,
// holding all 49 spatial outputs in registers. Channels staged in 2 smem
// chunks of 128 (zero-padded 9x9 halo).
// ---------------------------------------------------------------------------
__global__ void __launch_bounds__(256) conv_bce_kernel(
    const float* __restrict__ x,
    const float* __restrict__ conv_b,
    const float* __restrict__ score_w,
    const float* __restrict__ score_b) {
    __shared__ float xs[128 * 81];   // 128 channels x 9x9 padded plane
    __shared__ float red[HW_];

    int tid = threadIdx.x;
    int bt = blockIdx.x;
    int b = bt >> 5;     // /32
    int t = bt & 31;

    if (tid < HW_) red[tid] = 0.0f;

    const float* xp = x + ((size_t)b * C_ * T_ + t) * HW_;  // x[b,0,t,0,0]

    for (int dd = 0; dd < 2; dd++) {
        int d = tid + (dd << 8);
        float acc[HW_];
#pragma unroll
        for (int p = 0; p < HW_; p++) acc[p] = 0.0f;

        for (int ch = 0; ch < 2; ch++) {
            __syncthreads();
            for (int i = tid; i < 128 * 81; i += 256) xs[i] = 0.0f;
            __syncthreads();
            for (int i = tid; i < 128 * HW_; i += 256) {
                int c = i / HW_;
                int pos = i - c * HW_;
                int h = pos / W_;
                int w = pos - h * W_;
                xs[c * 81 + (h + 1) * 9 + (w + 1)] =
                    xp[(size_t)(ch * 128 + c) * (T_ * HW_) + pos];
            }
            __syncthreads();

            const float* wbase = g_wt + (size_t)(ch * 128) * TAPS * D_ + d;
            for (int c = 0; c < 128; c++) {
                float wv[TAPS];
#pragma unroll
                for (int tap = 0; tap < TAPS; tap++)
                    wv[tap] = wbase[(c * TAPS + tap) * D_];
                const float* xc = xs + c * 81;
#pragma unroll
                for (int r = 0; r < 9; r++) {
                    float xrow[9];
#pragma unroll
                    for (int q = 0; q < 9; q++) xrow[q] = xc[r * 9 + q];
#pragma unroll
                    for (int kh = 0; kh < 3; kh++) {
                        int h = r - kh;
                        if (h >= 0 && h < H_) {
#pragma unroll
                            for (int kw = 0; kw < 3; kw++) {
                                float w_ = wv[kh * 3 + kw];
#pragma unroll
                                for (int wc = 0; wc < W_; wc++)
                                    acc[h * W_ + wc] =
                                        fmaf(w_, xrow[wc + kw], acc[h * W_ + wc]);
                            }
                        }
                    }
                }
            }
        }
        // epilogue for this d: bias + relu + score weight, reduce over d
        float bias = conv_b[d];
        float sw = score_w[d];
#pragma unroll
        for (int p = 0; p < HW_; p++) {
            float v = acc[p] + bias;
            v = fmaxf(v, 0.0f);
            atomicAdd(&red[p], v * sw);
        }
    }
    __syncthreads();

    if (tid < HW_) {
        float logit = red[tid] + score_b[0];
        float y = g_cam[b * N_ + t * HW_ + tid];
        // bce = softplus(logit) - y*logit (pos_weight = 1)
        float ax = fabsf(logit);
        float sp = fmaxf(logit, 0.0f) + log1pf(expf(-ax));
        atomicAdd(&g_loss, sp - y * logit);
    }
}

// ---------------------------------------------------------------------------
// launch
// ---------------------------------------------------------------------------
extern "C" void kernel_launch(void* const* d_in, const int* in_sizes, int n_in,
                              void* d_out, int out_size) {
    const float* x   = (const float*)d_in[0];
    const float* lv  = (const float*)d_in[1];
    const float* ln  = (const float*)d_in[2];
    const float* wpv = (const float*)d_in[3];
    const float* wpn = (const float*)d_in[4];
    const float* cw  = (const float*)d_in[5];
    const float* cb  = (const float*)d_in[6];
    const float* sw  = (const float*)d_in[7];
    const float* sb  = (const float*)d_in[8];
    float* out = (float*)d_out;

    zero_loss_kernel<<<1, 1>>>();
    transpose_w_kernel<<<(KTOT * D_ + 255) / 256, 256>>>(cw);
    cam_kernel<<<B_, 256>>>(x, lv, ln, wpv, wpn);
    conv_bce_kernel<<<B_ * T_, 256>>>(x, cb, sw, sb);
    finalize_kernel<<<1, 1>>>(out);
}

// round 4
// speedup vs baseline: 7.8952x; 7.8952x over previous
#include <cuda_runtime.h>
#include <cuda_bf16.h>
#include <math.h>
#include <stdint.h>

// ---------------------------------------------------------------------------
// Problem constants
// ---------------------------------------------------------------------------
#define B_   64
#define C_   256
#define T_   32
#define H_   7
#define W_   7
#define HW_  49
#define N_   1568          // T*H*W
#define D_   512
#define KV_  97
#define KN_  300
#define NTOK 392
#define KTOT 2304          // C*9
#define MTOT 100352        // B*T*H*W
#define NCHUNK 36          // KTOT / 64

// Device scratch (static only)
__device__ __nv_bfloat16 g_xb[(size_t)B_ * N_ * C_];   // x transposed: [b][n][c]
__device__ __nv_bfloat16 g_wb[(size_t)D_ * KTOT];      // weights: [d][tap*256+c]
__device__ float g_rowv[B_ * N_];
__device__ float g_rown[B_ * N_];
__device__ float g_cam[B_ * N_];
__device__ float g_row[MTOT];                          // logits (pre score-bias)
__device__ float g_loss;

// ---------------------------------------------------------------------------
// PTX helpers (compute_103-safe: sm_80-era features only)
// ---------------------------------------------------------------------------
__device__ __forceinline__ uint32_t smem_u32(const void* p) {
    uint32_t a;
    asm("{ .reg .u64 t; cvta.to.shared.u64 t, %1; cvt.u32.u64 %0, t; }"
        : "=r"(a) : "l"(p));
    return a;
}
__device__ __forceinline__ void cp16(uint32_t dst, const void* src, int szbytes) {
    asm volatile("cp.async.cg.shared.global [%0], [%1], 16, %2;"
                 :: "r"(dst), "l"(src), "r"(szbytes) : "memory");
}
#define CP_COMMIT() asm volatile("cp.async.commit_group;" ::: "memory")
#define CP_WAIT1()  asm volatile("cp.async.wait_group 1;" ::: "memory")
#define CP_WAIT0()  asm volatile("cp.async.wait_group 0;" ::: "memory")

__device__ __forceinline__ uint32_t swz128(uint32_t off) {
    return off ^ ((off >> 3) & 0x70);
}
__device__ __forceinline__ void ldsm4(uint32_t* r, uint32_t addr) {
    asm volatile("ldmatrix.sync.aligned.m8n8.x4.shared.b16 {%0,%1,%2,%3}, [%4];"
                 : "=r"(r[0]), "=r"(r[1]), "=r"(r[2]), "=r"(r[3]) : "r"(addr));
}
__device__ __forceinline__ void mma_bf16(float* c, const uint32_t* a,
                                         const uint32_t* b) {
    asm volatile("mma.sync.aligned.m16n8k16.row.col.f32.bf16.bf16.f32 "
                 "{%0,%1,%2,%3}, {%4,%5,%6,%7}, {%8,%9}, {%0,%1,%2,%3};"
                 : "+f"(c[0]), "+f"(c[1]), "+f"(c[2]), "+f"(c[3])
                 : "r"(a[0]), "r"(a[1]), "r"(a[2]), "r"(a[3]),
                   "r"(b[0]), "r"(b[1]));
}

// ---------------------------------------------------------------------------
// small kernels
// ---------------------------------------------------------------------------
__global__ void zero_kernel() {
    int m = blockIdx.x * 256 + threadIdx.x;
    if (m < MTOT) g_row[m] = 0.0f;
    if (m == 0) g_loss = 0.0f;
}
__global__ void finalize_kernel(float* out) {
    out[0] = g_loss * (1.0f / (float)MTOT);
}

// weights: g_wb[d][tap*256+c] = bf16(conv_w[d][c*9+tap])
__global__ void wb_kernel(const float* __restrict__ cw) {
    int o = blockIdx.x * 256 + threadIdx.x;
    if (o >= D_ * KTOT) return;
    int d = o / KTOT;
    int k = o - d * KTOT;
    int tap = k >> 8;
    int c = k & 255;
    g_wb[o] = __float2bfloat16(cw[d * KTOT + c * 9 + tap]);
}

// x transpose: g_xb[b][n][c] = bf16(x[b][c][n]); grid (49, 8, 64), block (32,8)
__global__ void xb_kernel(const float* __restrict__ x) {
    __shared__ float tile[32][33];
    int b = blockIdx.z, n0 = blockIdx.x * 32, c0 = blockIdx.y * 32;
    int tx = threadIdx.x, ty = threadIdx.y;
    const float* xp = x + (size_t)b * C_ * N_;
#pragma unroll
    for (int i = 0; i < 4; i++)
        tile[ty + 8 * i][tx] = xp[(size_t)(c0 + ty + 8 * i) * N_ + n0 + tx];
    __syncthreads();
#pragma unroll
    for (int i = 0; i < 4; i++)
        g_xb[((size_t)b * N_ + n0 + ty + 8 * i) * C_ + c0 + tx] =
            __float2bfloat16(tile[tx][ty + 8 * i]);
}

// ---------------------------------------------------------------------------
// CAM dot kernel: grid (64, 7), 256 threads; each active thread owns one n.
// Computes both head dot-products (fp32 x, fp32 weights).
// ---------------------------------------------------------------------------
__global__ void __launch_bounds__(256) cam_dot_kernel(
    const float* __restrict__ x,
    const float* __restrict__ lv, const float* __restrict__ ln,
    const float* __restrict__ wpv, const float* __restrict__ wpn) {
    __shared__ float wsv[C_], wsn[C_];
    __shared__ float rv[256];
    __shared__ int   ri[256];
    int tid = threadIdx.x;
    int b = blockIdx.x;

    // block argmax for both heads (redundant across 7 blocks; cheap)
    for (int head = 0; head < 2; head++) {
        const float* lg = head ? (ln + b * KN_) : (lv + b * KV_);
        int K = head ? KN_ : KV_;
        float best = -INFINITY; int bi = 0x7fffffff;
        for (int k = tid; k < K; k += 256) {
            float val = lg[k];
            if (val > best) { best = val; bi = k; }
        }
        rv[tid] = best; ri[tid] = bi;
        __syncthreads();
        for (int s = 128; s > 0; s >>= 1) {
            if (tid < s) {
                float ov = rv[tid + s]; int oi = ri[tid + s];
                if (ov > rv[tid] || (ov == rv[tid] && oi < ri[tid])) {
                    rv[tid] = ov; ri[tid] = oi;
                }
            }
            __syncthreads();
        }
        int top = ri[0];
        __syncthreads();
        const float* wp = head ? (wpn + top * C_) : (wpv + top * C_);
        float* ws = head ? wsn : wsv;
        if (tid < C_) ws[tid] = wp[tid];
        __syncthreads();
    }

    int n = blockIdx.y * 224 + tid;
    if (tid >= 224 || n >= N_) return;
    const float* xb = x + (size_t)b * C_ * N_;
    float av = 0.0f, an = 0.0f;
#pragma unroll 8
    for (int c = 0; c < C_; c++) {
        float xv = xb[(size_t)c * N_ + n];
        av = fmaf(wsv[c], xv, av);
        an = fmaf(wsn[c], xv, an);
    }
    g_rowv[b * N_ + n] = av;
    g_rown[b * N_ + n] = an;
}

// ---------------------------------------------------------------------------
// CAM threshold kernel: grid 64, 512 threads. Min-max norm + exact top-392
// threshold via bitonic sort; builds cam_gt = max(camv, camn).
// ---------------------------------------------------------------------------
__device__ float norm_thresh512(float* row, float* sbuf, float* rmin, float* rmax) {
    int tid = threadIdx.x;
    float mn = INFINITY, mx = -INFINITY;
    for (int n = tid; n < N_; n += 512) {
        float v = row[n];
        mn = fminf(mn, v);
        mx = fmaxf(mx, v);
    }
    rmin[tid] = mn; rmax[tid] = mx;
    __syncthreads();
    for (int s = 256; s > 0; s >>= 1) {
        if (tid < s) {
            rmin[tid] = fminf(rmin[tid], rmin[tid + s]);
            rmax[tid] = fmaxf(rmax[tid], rmax[tid + s]);
        }
        __syncthreads();
    }
    mn = rmin[0]; mx = rmax[0];
    __syncthreads();
    float inv = 1.0f / (mx - mn);
    for (int n = tid; n < N_; n += 512)
        row[n] = (row[n] - mn) * inv;
    __syncthreads();
    for (int i = tid; i < 2048; i += 512)
        sbuf[i] = (i < N_) ? row[i] : -1.0f;
    __syncthreads();
    for (int k = 2; k <= 2048; k <<= 1) {
        for (int j = k >> 1; j > 0; j >>= 1) {
            for (int i = tid; i < 2048; i += 512) {
                int ixj = i ^ j;
                if (ixj > i) {
                    float a = sbuf[i], c = sbuf[ixj];
                    bool up = ((i & k) == 0);
                    if ((a > c) == up) { sbuf[i] = c; sbuf[ixj] = a; }
                }
            }
            __syncthreads();
        }
    }
    float thr = sbuf[2048 - NTOK];
    __syncthreads();
    return thr;
}

__global__ void __launch_bounds__(512) cam_thresh_kernel() {
    __shared__ float row[N_];
    __shared__ float sbuf[2048];
    __shared__ float rA[512], rB[512];
    int tid = threadIdx.x;
    int b = blockIdx.x;

    for (int n = tid; n < N_; n += 512) row[n] = g_rowv[b * N_ + n];
    __syncthreads();
    float thrv = norm_thresh512(row, sbuf, rA, rB);
    for (int n = tid; n < N_; n += 512)
        g_cam[b * N_ + n] = (row[n] >= thrv) ? row[n] : 0.0f;
    __syncthreads();

    for (int n = tid; n < N_; n += 512) row[n] = g_rown[b * N_ + n];
    __syncthreads();
    float thrn = norm_thresh512(row, sbuf, rA, rB);
    for (int n = tid; n < N_; n += 512) {
        float cn = (row[n] >= thrn) ? row[n] : 0.0f;
        g_cam[b * N_ + n] = fmaxf(g_cam[b * N_ + n], cn);
    }
}

// ---------------------------------------------------------------------------
// Implicit-GEMM conv via mma.sync bf16 (legacy tensor path; compute_103-safe)
// CTA tile 128x256, 8 warps (2x4), warp tile 64x64, K chunks of 64, double
// buffered cp.async. Epilogue: bias+relu+score dot -> g_row[m] partials.
// ---------------------------------------------------------------------------
#define SA_(s)   ((uint32_t)(s) * 16384u)               // 2 x 16KB
#define SB_(s)   (32768u + (uint32_t)(s) * 32768u)      // 2 x 32KB
#define OFF_RED  98304u                                 // 128 floats
#define OFF_CB   98816u                                 // 256 floats
#define OFF_SW   99840u                                 // 256 floats
#define SMEM_DYN 100864u

__global__ void __launch_bounds__(256, 1) gemm_kernel(
    const float* __restrict__ conv_b,
    const float* __restrict__ score_w) {
    extern __shared__ char smem[];
    uint32_t sbase = smem_u32(smem);
    int tid = threadIdx.x, wid = tid >> 5, lane = tid & 31;

    int idx = blockIdx.x;
    int nt = idx & 1;            // ntile fast -> A tile L2 reuse
    int mt = idx >> 1;
    int m0 = mt * 128;
    int dbase = nt * 256;

    float* s_red = (float*)(smem + OFF_RED);
    float* s_cb  = (float*)(smem + OFF_CB);
    float* s_sw  = (float*)(smem + OFF_SW);
    if (tid < 128) s_red[tid] = 0.0f;
    if (tid < 256) { s_cb[tid] = conv_b[dbase + tid]; s_sw[tid] = score_w[dbase + tid]; }

    // Per-thread A-row info: rows rb + 32j
    int rb = tid >> 3, seg = tid & 7;
    int hh[4], ww[4], bt49[4];
#pragma unroll
    for (int j = 0; j < 4; j++) {
        int m = m0 + rb + 32 * j;
        int b = m / N_;
        int rem = m - b * N_;
        int t = rem / HW_;
        int p = rem - t * HW_;
        hh[j] = p / W_;
        ww[j] = p - hh[j] * W_;
        bt49[j] = (b * T_ + t) * HW_;
    }
    uint32_t aoff[4];
#pragma unroll
    for (int j = 0; j < 4; j++) aoff[j] = (uint32_t)(rb + 32 * j) * 128u + seg * 16u;

    auto load_chunk = [&](int kc, int stage) {
        int tap = kc >> 2, c0 = (kc & 3) << 6;
        int dh = tap / 3 - 1, dw = tap - (tap / 3) * 3 - 1;
        uint32_t sa = sbase + SA_(stage);
        uint32_t sbB = sbase + SB_(stage);
        // A: 4 x 16B per thread
#pragma unroll
        for (int j = 0; j < 4; j++) {
            int h2 = hh[j] + dh, w2 = ww[j] + dw;
            bool ok = (h2 >= 0) & (h2 < H_) & (w2 >= 0) & (w2 < W_);
            uint32_t eoff = (uint32_t)(ok ? (bt49[j] + h2 * W_ + w2) : 0) * (uint32_t)C_
                            + (uint32_t)c0 + seg * 8u;
            cp16(sa + swz128(aoff[j]), g_xb + eoff, ok ? 16 : 0);
        }
        // B: 8 x 16B per thread (rows = d-local)
        uint32_t koff = (uint32_t)(tap * 256 + c0) + seg * 8u;
#pragma unroll
        for (int j = 0; j < 8; j++) {
            uint32_t drow = (uint32_t)(rb + 32 * j);
            uint32_t eoff = (uint32_t)(dbase + drow) * (uint32_t)KTOT + koff;
            cp16(sbB + swz128(drow * 128u + seg * 16u), g_wb + eoff, 16);
        }
    };

    float acc[4][8][4];
#pragma unroll
    for (int i = 0; i < 4; i++)
#pragma unroll
        for (int j = 0; j < 8; j++)
#pragma unroll
            for (int c = 0; c < 4; c++) acc[i][j][c] = 0.0f;

    int wm = wid >> 2, wn = wid & 3;
    int q = lane >> 3, g = lane & 7;
    // ldmatrix lane row/k offsets
    int a_row = (q & 1) * 8 + g, a_k = (q >> 1) * 8;
    int b_row = (q >> 1) * 8 + g, b_k = (q & 1) * 8;

    load_chunk(0, 0);
    CP_COMMIT();

    for (int kc = 0; kc < NCHUNK; kc++) {
        int st = kc & 1;
        if (kc + 1 < NCHUNK) {
            load_chunk(kc + 1, st ^ 1);
            CP_COMMIT();
            CP_WAIT1();
        } else {
            CP_WAIT0();
        }
        __syncthreads();

        uint32_t sa = sbase + SA_(st);
        uint32_t sbB = sbase + SB_(st);
#pragma unroll
        for (int k0 = 0; k0 < 64; k0 += 16) {
            uint32_t af[4][4], bf[4][4];
#pragma unroll
            for (int i = 0; i < 4; i++)
                ldsm4(af[i], sa + swz128((uint32_t)(wm * 64 + i * 16 + a_row) * 128u
                                         + (uint32_t)(k0 + a_k) * 2u));
#pragma unroll
            for (int j2 = 0; j2 < 4; j2++)
                ldsm4(bf[j2], sbB + swz128((uint32_t)(wn * 64 + j2 * 16 + b_row) * 128u
                                           + (uint32_t)(k0 + b_k) * 2u));
#pragma unroll
            for (int i = 0; i < 4; i++)
#pragma unroll
                for (int j = 0; j < 8; j++) {
                    const uint32_t* bp = (j & 1) ? (bf[j >> 1] + 2) : bf[j >> 1];
                    mma_bf16(acc[i][j], af[i], bp);
                }
        }
        __syncthreads();
    }

    // Epilogue: bias + relu + score dot; per-row partial sums
    int t4 = lane & 3, gg = lane >> 2;
#pragma unroll
    for (int i = 0; i < 4; i++) {
        int r0 = wm * 64 + i * 16 + gg;
        float s0 = 0.0f, s1 = 0.0f;
#pragma unroll
        for (int j = 0; j < 8; j++) {
            int dl = wn * 64 + j * 8 + 2 * t4;
            float cb0 = s_cb[dl], cb1 = s_cb[dl + 1];
            float sw0 = s_sw[dl], sw1 = s_sw[dl + 1];
            s0 = fmaf(fmaxf(acc[i][j][0] + cb0, 0.0f), sw0, s0);
            s0 = fmaf(fmaxf(acc[i][j][1] + cb1, 0.0f), sw1, s0);
            s1 = fmaf(fmaxf(acc[i][j][2] + cb0, 0.0f), sw0, s1);
            s1 = fmaf(fmaxf(acc[i][j][3] + cb1, 0.0f), sw1, s1);
        }
        s0 += __shfl_xor_sync(0xFFFFFFFFu, s0, 1);
        s0 += __shfl_xor_sync(0xFFFFFFFFu, s0, 2);
        s1 += __shfl_xor_sync(0xFFFFFFFFu, s1, 1);
        s1 += __shfl_xor_sync(0xFFFFFFFFu, s1, 2);
        if (t4 == 0) {
            atomicAdd(&s_red[r0], s0);
            atomicAdd(&s_red[r0 + 8], s1);
        }
    }
    __syncthreads();
    if (tid < 128) atomicAdd(&g_row[m0 + tid], s_red[tid]);
}

// ---------------------------------------------------------------------------
// BCE: logits in g_row, targets in g_cam -> g_loss
// ---------------------------------------------------------------------------
__global__ void __launch_bounds__(256) bce_kernel(const float* __restrict__ sb) {
    __shared__ float red[256];
    int tid = threadIdx.x;
    int m = blockIdx.x * 256 + tid;
    float v = 0.0f;
    if (m < MTOT) {
        float logit = g_row[m] + sb[0];
        float y = g_cam[m];
        float ax = fabsf(logit);
        float sp = fmaxf(logit, 0.0f) + log1pf(expf(-ax));
        v = sp - y * logit;
    }
    red[tid] = v;
    __syncthreads();
    for (int s = 128; s > 0; s >>= 1) {
        if (tid < s) red[tid] += red[tid + s];
        __syncthreads();
    }
    if (tid == 0) atomicAdd(&g_loss, red[0]);
}

// ---------------------------------------------------------------------------
// launch
// ---------------------------------------------------------------------------
extern "C" void kernel_launch(void* const* d_in, const int* in_sizes, int n_in,
                              void* d_out, int out_size) {
    const float* x   = (const float*)d_in[0];
    const float* lv  = (const float*)d_in[1];
    const float* ln  = (const float*)d_in[2];
    const float* wpv = (const float*)d_in[3];
    const float* wpn = (const float*)d_in[4];
    const float* cw  = (const float*)d_in[5];
    const float* cb  = (const float*)d_in[6];
    const float* sw  = (const float*)d_in[7];
    const float* sbv = (const float*)d_in[8];
    float* out = (float*)d_out;

    cudaFuncSetAttribute(gemm_kernel,
                         cudaFuncAttributeMaxDynamicSharedMemorySize, SMEM_DYN);

    zero_kernel<<<(MTOT + 255) / 256, 256>>>();
    wb_kernel<<<(D_ * KTOT + 255) / 256, 256>>>(cw);
    {
        dim3 g(49, 8, 64), b(32, 8);
        xb_kernel<<<g, b>>>(x);
    }
    {
        dim3 g(B_, 7);
        cam_dot_kernel<<<g, 256>>>(x, lv, ln, wpv, wpn);
    }
    cam_thresh_kernel<<<B_, 512>>>();
    gemm_kernel<<<784 * 2, 256, SMEM_DYN>>>(cb, sw);
    bce_kernel<<<(MTOT + 255) / 256, 256>>>(sbv);
    finalize_kernel<<<1, 1>>>(out);
}

// round 5
// speedup vs baseline: 8.4408x; 1.0691x over previous
#include <cuda_runtime.h>
#include <cuda_fp16.h>
#include <math.h>
#include <stdint.h>

// ---------------------------------------------------------------------------
// Problem constants
// ---------------------------------------------------------------------------
#define B_   64
#define C_   256
#define T_   32
#define H_   7
#define W_   7
#define HW_  49
#define N_   1568          // T*H*W
#define D_   512
#define KV_  97
#define KN_  300
#define NTOK 392
#define KTOT 2304          // C*9
#define MTOT 100352        // B*T*H*W
#define NCHUNK 36          // KTOT / 64

// Device scratch (static only)
__device__ __half g_xh[(size_t)B_ * N_ * C_];   // x transposed fp16: [b][n][c]
__device__ __half g_wh[(size_t)D_ * KTOT];      // weights fp16: [d][tap*256+c]
__device__ float g_wselv[B_ * C_];              // selected class weight rows
__device__ float g_wseln[B_ * C_];
__device__ float g_rowv[B_ * N_];
__device__ float g_rown[B_ * N_];
__device__ float g_row[MTOT];                   // logits (pre score-bias)
__device__ float g_loss;

// ---------------------------------------------------------------------------
// PTX helpers (compute_103-safe: sm_80-era features only)
// ---------------------------------------------------------------------------
__device__ __forceinline__ uint32_t smem_u32(const void* p) {
    uint32_t a;
    asm("{ .reg .u64 t; cvta.to.shared.u64 t, %1; cvt.u32.u64 %0, t; }"
        : "=r"(a) : "l"(p));
    return a;
}
__device__ __forceinline__ void cp16(uint32_t dst, const void* src, int szbytes) {
    asm volatile("cp.async.cg.shared.global [%0], [%1], 16, %2;"
                 :: "r"(dst), "l"(src), "r"(szbytes) : "memory");
}
#define CP_COMMIT() asm volatile("cp.async.commit_group;" ::: "memory")
#define CP_WAIT1()  asm volatile("cp.async.wait_group 1;" ::: "memory")
#define CP_WAIT0()  asm volatile("cp.async.wait_group 0;" ::: "memory")

__device__ __forceinline__ uint32_t swz128(uint32_t off) {
    return off ^ ((off >> 3) & 0x70);
}
__device__ __forceinline__ void ldsm4(uint32_t* r, uint32_t addr) {
    asm volatile("ldmatrix.sync.aligned.m8n8.x4.shared.b16 {%0,%1,%2,%3}, [%4];"
                 : "=r"(r[0]), "=r"(r[1]), "=r"(r[2]), "=r"(r[3]) : "r"(addr));
}
// fp16 x fp16 -> fp16 accumulate
__device__ __forceinline__ void mma_f16(uint32_t* c, const uint32_t* a,
                                        const uint32_t* b) {
    asm volatile("mma.sync.aligned.m16n8k16.row.col.f16.f16.f16.f16 "
                 "{%0,%1}, {%2,%3,%4,%5}, {%6,%7}, {%0,%1};"
                 : "+r"(c[0]), "+r"(c[1])
                 : "r"(a[0]), "r"(a[1]), "r"(a[2]), "r"(a[3]),
                   "r"(b[0]), "r"(b[1]));
}

// ---------------------------------------------------------------------------
// small kernels
// ---------------------------------------------------------------------------
__global__ void zero_kernel() {
    int m = blockIdx.x * 256 + threadIdx.x;
    if (m < MTOT) { g_row[m] = 0.0f; g_rowv[m] = 0.0f; g_rown[m] = 0.0f; }
    if (m == 0) g_loss = 0.0f;
}
__global__ void finalize_kernel(float* out) {
    out[0] = g_loss * (1.0f / (float)MTOT);
}

// weights: g_wh[d][tap*256+c] = fp16(conv_w[d][c*9+tap])
__global__ void wh_kernel(const float* __restrict__ cw) {
    int o = blockIdx.x * 256 + threadIdx.x;
    if (o >= D_ * KTOT) return;
    int d = o / KTOT;
    int k = o - d * KTOT;
    int tap = k >> 8;
    int c = k & 255;
    g_wh[o] = __float2half(cw[d * KTOT + c * 9 + tap]);
}

// per-b argmax over both heads; copy the selected class weight rows
__global__ void __launch_bounds__(256) argmax_sel_kernel(
    const float* __restrict__ lv, const float* __restrict__ ln,
    const float* __restrict__ wpv, const float* __restrict__ wpn) {
    __shared__ float rv[256];
    __shared__ int   ri[256];
    int tid = threadIdx.x;
    int b = blockIdx.x;
    for (int head = 0; head < 2; head++) {
        const float* lg = head ? (ln + b * KN_) : (lv + b * KV_);
        int K = head ? KN_ : KV_;
        float best = -INFINITY; int bi = 0x7fffffff;
        for (int k = tid; k < K; k += 256) {
            float val = lg[k];
            if (val > best) { best = val; bi = k; }
        }
        rv[tid] = best; ri[tid] = bi;
        __syncthreads();
        for (int s = 128; s > 0; s >>= 1) {
            if (tid < s) {
                float ov = rv[tid + s]; int oi = ri[tid + s];
                if (ov > rv[tid] || (ov == rv[tid] && oi < ri[tid])) {
                    rv[tid] = ov; ri[tid] = oi;
                }
            }
            __syncthreads();
        }
        int top = ri[0];
        __syncthreads();
        if (head) g_wseln[b * C_ + tid] = wpn[top * C_ + tid];
        else      g_wselv[b * C_ + tid] = wpv[top * C_ + tid];
    }
}

// ---------------------------------------------------------------------------
// x transpose + fused CAM partial dots.
// grid (49, 8, 64), block (32, 8). Writes g_xh and atomically accumulates
// both head dot products in fp32 (exact CAM path, no second x read).
// ---------------------------------------------------------------------------
__global__ void __launch_bounds__(256) xb_cam_kernel(const float* __restrict__ x) {
    __shared__ float tile[32][33];
    __shared__ float wv[32], wn_[32];
    __shared__ float red[2][8][33];
    int b = blockIdx.z, n0 = blockIdx.x * 32, c0 = blockIdx.y * 32;
    int tx = threadIdx.x, ty = threadIdx.y;
    int tid = ty * 32 + tx;
    const float* xp = x + (size_t)b * C_ * N_;

    if (tid < 32)      wv[tid] = g_wselv[b * C_ + c0 + tid];
    else if (tid < 64) wn_[tid - 32] = g_wseln[b * C_ + c0 + tid - 32];

#pragma unroll
    for (int i = 0; i < 4; i++)
        tile[ty + 8 * i][tx] = xp[(size_t)(c0 + ty + 8 * i) * N_ + n0 + tx];
    __syncthreads();

    // transposed fp16 write
#pragma unroll
    for (int i = 0; i < 4; i++)
        g_xh[((size_t)b * N_ + n0 + ty + 8 * i) * C_ + c0 + tx] =
            __float2half(tile[tx][ty + 8 * i]);

    // CAM partials
    float sv = 0.0f, sn = 0.0f;
#pragma unroll
    for (int i = 0; i < 4; i++) {
        float xv = tile[ty + 8 * i][tx];
        sv = fmaf(wv[ty + 8 * i], xv, sv);
        sn = fmaf(wn_[ty + 8 * i], xv, sn);
    }
    red[0][ty][tx] = sv;
    red[1][ty][tx] = sn;
    __syncthreads();
    if (ty < 2) {
        float s = 0.0f;
#pragma unroll
        for (int k = 0; k < 8; k++) s += red[ty][k][tx];
        float* dst = ty ? g_rown : g_rowv;
        atomicAdd(&dst[b * N_ + n0 + tx], s);
    }
}

// ---------------------------------------------------------------------------
// CAM threshold kernel: grid (64, 2), 512 threads. Min-max norm + exact
// top-392 threshold (bitonic sort); writes thresholded values in place.
// ---------------------------------------------------------------------------
__global__ void __launch_bounds__(512) cam_thresh_kernel() {
    __shared__ float row[N_];
    __shared__ float sbuf[2048];
    __shared__ float rA[512], rB[512];
    int tid = threadIdx.x;
    int b = blockIdx.x;
    float* src = blockIdx.y ? g_rown : g_rowv;

    for (int n = tid; n < N_; n += 512) row[n] = src[b * N_ + n];
    __syncthreads();

    float mn = INFINITY, mx = -INFINITY;
    for (int n = tid; n < N_; n += 512) {
        float v = row[n];
        mn = fminf(mn, v);
        mx = fmaxf(mx, v);
    }
    rA[tid] = mn; rB[tid] = mx;
    __syncthreads();
    for (int s = 256; s > 0; s >>= 1) {
        if (tid < s) {
            rA[tid] = fminf(rA[tid], rA[tid + s]);
            rB[tid] = fmaxf(rB[tid], rB[tid + s]);
        }
        __syncthreads();
    }
    mn = rA[0]; mx = rB[0];
    __syncthreads();
    float inv = 1.0f / (mx - mn);
    for (int n = tid; n < N_; n += 512)
        row[n] = (row[n] - mn) * inv;
    __syncthreads();
    for (int i = tid; i < 2048; i += 512)
        sbuf[i] = (i < N_) ? row[i] : -1.0f;
    __syncthreads();
    for (int k = 2; k <= 2048; k <<= 1) {
        for (int j = k >> 1; j > 0; j >>= 1) {
            for (int i = tid; i < 2048; i += 512) {
                int ixj = i ^ j;
                if (ixj > i) {
                    float a = sbuf[i], c = sbuf[ixj];
                    bool up = ((i & k) == 0);
                    if ((a > c) == up) { sbuf[i] = c; sbuf[ixj] = a; }
                }
            }
            __syncthreads();
        }
    }
    float thr = sbuf[2048 - NTOK];
    __syncthreads();
    for (int n = tid; n < N_; n += 512)
        src[b * N_ + n] = (row[n] >= thr) ? row[n] : 0.0f;
}

// ---------------------------------------------------------------------------
// Implicit-GEMM conv via mma.sync fp16 (fp16 accum => 256x256 CTA tile).
// 512 threads, 16 warps (4x4), warp tile 64x64. K chunks of 64, double
// buffered cp.async. Epilogue: bias+relu+score dot -> g_row[m] partials.
// ---------------------------------------------------------------------------
#define SA_(s)   ((uint32_t)(s) * 32768u)               // 2 x 32KB
#define SB_(s)   (65536u + (uint32_t)(s) * 32768u)      // 2 x 32KB
#define OFF_RED  131072u                                // 256 floats
#define OFF_CB   132096u                                // 256 floats
#define OFF_SW   133120u                                // 256 floats
#define SMEM_DYN 134144u

__global__ void __launch_bounds__(512, 1) gemm_kernel(
    const float* __restrict__ conv_b,
    const float* __restrict__ score_w) {
    extern __shared__ char smem[];
    uint32_t sbase = smem_u32(smem);
    int tid = threadIdx.x, wid = tid >> 5, lane = tid & 31;

    int idx = blockIdx.x;
    int nt = idx & 1;            // ntile fast -> A tile L2 reuse
    int mt = idx >> 1;
    int m0 = mt * 256;
    int dbase = nt * 256;

    float* s_red = (float*)(smem + OFF_RED);
    float* s_cb  = (float*)(smem + OFF_CB);
    float* s_sw  = (float*)(smem + OFF_SW);
    if (tid < 256) {
        s_red[tid] = 0.0f;
        s_cb[tid] = conv_b[dbase + tid];
        s_sw[tid] = score_w[dbase + tid];
    }

    // Per-thread A-row info: rows rb + 64j, j=0..3
    int rb = tid >> 3, seg = tid & 7;
    int hh[4], ww[4], bt49[4];
#pragma unroll
    for (int j = 0; j < 4; j++) {
        int m = m0 + rb + 64 * j;
        int b = m / N_;
        int rem = m - b * N_;
        int t = rem / HW_;
        int p = rem - t * HW_;
        hh[j] = p / W_;
        ww[j] = p - hh[j] * W_;
        bt49[j] = (b * T_ + t) * HW_;
    }

    auto load_chunk = [&](int kc, int stage) {
        int tap = kc >> 2, c0 = (kc & 3) << 6;
        int dh = tap / 3 - 1, dw = tap - (tap / 3) * 3 - 1;
        uint32_t sa = sbase + SA_(stage);
        uint32_t sbB = sbase + SB_(stage);
        // A: 4 x 16B per thread (rows rb + 64j)
#pragma unroll
        for (int j = 0; j < 4; j++) {
            int h2 = hh[j] + dh, w2 = ww[j] + dw;
            bool ok = (h2 >= 0) & (h2 < H_) & (w2 >= 0) & (w2 < W_);
            uint32_t eoff = (uint32_t)(ok ? (bt49[j] + h2 * W_ + w2) : 0) * (uint32_t)C_
                            + (uint32_t)c0 + seg * 8u;
            uint32_t doff = (uint32_t)(rb + 64 * j) * 128u + seg * 16u;
            cp16(sa + swz128(doff), g_xh + eoff, ok ? 16 : 0);
        }
        // B: 4 x 16B per thread (d rows rb + 64j)
        uint32_t koff = (uint32_t)(tap * 256 + c0) + seg * 8u;
#pragma unroll
        for (int j = 0; j < 4; j++) {
            uint32_t drow = (uint32_t)(rb + 64 * j);
            uint32_t eoff = (uint32_t)(dbase + drow) * (uint32_t)KTOT + koff;
            cp16(sbB + swz128(drow * 128u + seg * 16u), g_wh + eoff, 16);
        }
    };

    uint32_t acc[4][8][2];
#pragma unroll
    for (int i = 0; i < 4; i++)
#pragma unroll
        for (int j = 0; j < 8; j++) { acc[i][j][0] = 0u; acc[i][j][1] = 0u; }

    int wm = wid >> 2, wn = wid & 3;
    int q = lane >> 3, g = lane & 7;
    int a_row = (q & 1) * 8 + g, a_k = (q >> 1) * 8;
    int b_row = (q >> 1) * 8 + g, b_k = (q & 1) * 8;

    load_chunk(0, 0);
    CP_COMMIT();

    for (int kc = 0; kc < NCHUNK; kc++) {
        int st = kc & 1;
        if (kc + 1 < NCHUNK) {
            load_chunk(kc + 1, st ^ 1);
            CP_COMMIT();
            CP_WAIT1();
        } else {
            CP_WAIT0();
        }
        __syncthreads();

        uint32_t sa = sbase + SA_(st);
        uint32_t sbB = sbase + SB_(st);
#pragma unroll
        for (int k0 = 0; k0 < 64; k0 += 16) {
            uint32_t af[4][4], bf[4][4];
#pragma unroll
            for (int i = 0; i < 4; i++)
                ldsm4(af[i], sa + swz128((uint32_t)(wm * 64 + i * 16 + a_row) * 128u
                                         + (uint32_t)(k0 + a_k) * 2u));
#pragma unroll
            for (int j2 = 0; j2 < 4; j2++)
                ldsm4(bf[j2], sbB + swz128((uint32_t)(wn * 64 + j2 * 16 + b_row) * 128u
                                           + (uint32_t)(k0 + b_k) * 2u));
#pragma unroll
            for (int i = 0; i < 4; i++)
#pragma unroll
                for (int j = 0; j < 8; j++) {
                    const uint32_t* bp = (j & 1) ? (bf[j >> 1] + 2) : bf[j >> 1];
                    mma_f16(acc[i][j], af[i], bp);
                }
        }
        __syncthreads();
    }

    // Epilogue: bias + relu + score dot; per-row partial sums
    int t4 = lane & 3, gg = lane >> 2;
#pragma unroll
    for (int i = 0; i < 4; i++) {
        int r0 = wm * 64 + i * 16 + gg;
        float s0 = 0.0f, s1 = 0.0f;
#pragma unroll
        for (int j = 0; j < 8; j++) {
            int dl = wn * 64 + j * 8 + 2 * t4;
            float cb0 = s_cb[dl], cb1 = s_cb[dl + 1];
            float sw0 = s_sw[dl], sw1 = s_sw[dl + 1];
            float2 p0 = __half22float2(*(const __half2*)&acc[i][j][0]);
            float2 p1 = __half22float2(*(const __half2*)&acc[i][j][1]);
            s0 = fmaf(fmaxf(p0.x + cb0, 0.0f), sw0, s0);
            s0 = fmaf(fmaxf(p0.y + cb1, 0.0f), sw1, s0);
            s1 = fmaf(fmaxf(p1.x + cb0, 0.0f), sw0, s1);
            s1 = fmaf(fmaxf(p1.y + cb1, 0.0f), sw1, s1);
        }
        s0 += __shfl_xor_sync(0xFFFFFFFFu, s0, 1);
        s0 += __shfl_xor_sync(0xFFFFFFFFu, s0, 2);
        s1 += __shfl_xor_sync(0xFFFFFFFFu, s1, 1);
        s1 += __shfl_xor_sync(0xFFFFFFFFu, s1, 2);
        if (t4 == 0) {
            atomicAdd(&s_red[r0], s0);
            atomicAdd(&s_red[r0 + 8], s1);
        }
    }
    __syncthreads();
    if (tid < 256) atomicAdd(&g_row[m0 + tid], s_red[tid]);
}

// ---------------------------------------------------------------------------
// BCE: logits in g_row, targets = max(g_rowv, g_rown) -> g_loss
// ---------------------------------------------------------------------------
__global__ void __launch_bounds__(256) bce_kernel(const float* __restrict__ sb) {
    __shared__ float red[256];
    int tid = threadIdx.x;
    int m = blockIdx.x * 256 + tid;
    float v = 0.0f;
    if (m < MTOT) {
        float logit = g_row[m] + sb[0];
        float y = fmaxf(g_rowv[m], g_rown[m]);
        float ax = fabsf(logit);
        float sp = fmaxf(logit, 0.0f) + log1pf(expf(-ax));
        v = sp - y * logit;
    }
    red[tid] = v;
    __syncthreads();
    for (int s = 128; s > 0; s >>= 1) {
        if (tid < s) red[tid] += red[tid + s];
        __syncthreads();
    }
    if (tid == 0) atomicAdd(&g_loss, red[0]);
}

// ---------------------------------------------------------------------------
// launch
// ---------------------------------------------------------------------------
extern "C" void kernel_launch(void* const* d_in, const int* in_sizes, int n_in,
                              void* d_out, int out_size) {
    const float* x   = (const float*)d_in[0];
    const float* lv  = (const float*)d_in[1];
    const float* ln  = (const float*)d_in[2];
    const float* wpv = (const float*)d_in[3];
    const float* wpn = (const float*)d_in[4];
    const float* cw  = (const float*)d_in[5];
    const float* cb  = (const float*)d_in[6];
    const float* sw  = (const float*)d_in[7];
    const float* sbv = (const float*)d_in[8];
    float* out = (float*)d_out;

    cudaFuncSetAttribute(gemm_kernel,
                         cudaFuncAttributeMaxDynamicSharedMemorySize, SMEM_DYN);

    zero_kernel<<<(MTOT + 255) / 256, 256>>>();
    wh_kernel<<<(D_ * KTOT + 255) / 256, 256>>>(cw);
    argmax_sel_kernel<<<B_, 256>>>(lv, ln, wpv, wpn);
    {
        dim3 g(49, 8, 64), b(32, 8);
        xb_cam_kernel<<<g, b>>>(x);
    }
    {
        dim3 g(B_, 2);
        cam_thresh_kernel<<<g, 512>>>();
    }
    gemm_kernel<<<392 * 2, 512, SMEM_DYN>>>(cb, sw);
    bce_kernel<<<(MTOT + 255) / 256, 256>>>(sbv);
    finalize_kernel<<<1, 1>>>(out);
}